// round 2
// baseline (speedup 1.0000x reference)
#include <cuda_runtime.h>
#include <math.h>

#define N_NODES 50000
#define N_EDGES 800000
#define NHEADS  8
#define MULT    16

#define SCAN_TOT   50176           // 196 * 256, covers N_NODES
#define SCAN_NB    196

// Scratch (device globals — no allocation allowed in kernel_launch)
__device__ float g_e[(size_t)N_EDGES * NHEADS];   // exp scores -> normalized attn (25.6 MB)
__device__ float g_s[(size_t)N_NODES * NHEADS];   // denominators -> inverted (1.6 MB)
__device__ int   g_cnt[SCAN_TOT];                 // per-node (col) edge counts
__device__ int   g_excl[SCAN_TOT];                // per-block exclusive prefix
__device__ int   g_bsum[256];                     // block totals
__device__ int   g_bbase[256];                    // scanned block bases
__device__ int   g_csr[N_NODES + 1];              // final CSR offsets
__device__ int   g_cur[N_NODES];                  // running cursors for id scatter
__device__ int   g_elist[N_EDGES];                // edge ids grouped by col

// ---------------------------------------------------------------------------
// Pass 1: one thread per (edge, head): exp(score) + denominator atomics.
// h==0 thread also histograms col for the CSR build.
// ---------------------------------------------------------------------------
__global__ void __launch_bounds__(256) pass1_scores(
    const float* __restrict__ k0, const float* __restrict__ k1,
    const float* __restrict__ q0, const float* __restrict__ q1,
    const int* __restrict__ row_idx, const int* __restrict__ col_idx)
{
    int t = blockIdx.x * blockDim.x + threadIdx.x;
    if (t >= N_EDGES * NHEADS) return;
    int e = t >> 3;
    int h = t & 7;

    int col = __ldg(col_idx + e);

    float2 ka = *(const float2*)(k0 + (size_t)e   * 16 + 2 * h);
    float2 qa = *(const float2*)(q0 + (size_t)col * 16 + 2 * h);
    float dot = ka.x * qa.x + ka.y * qa.y;

    const float2* k1p = (const float2*)(k1 + (size_t)e   * 48 + 6 * h);
    const float2* q1p = (const float2*)(q1 + (size_t)col * 48 + 6 * h);
#pragma unroll
    for (int j = 0; j < 3; j++) {
        float2 kb = k1p[j];
        float2 qb = q1p[j];
        dot += kb.x * qb.x + kb.y * qb.y;
    }

    float w = expf(dot * 0.125f);   // 1/sqrt(64)
    g_e[t] = w;

    int rw = __ldg(row_idx + e);
    atomicAdd(&g_s[rw * NHEADS + h], w);

    if (h == 0) atomicAdd(&g_cnt[col], 1);
}

// ---------------------------------------------------------------------------
// Invert denominators.
// ---------------------------------------------------------------------------
__global__ void __launch_bounds__(256) invert_s()
{
    int t = blockIdx.x * blockDim.x + threadIdx.x;
    if (t >= N_NODES * NHEADS) return;
    float s = g_s[t];
    g_s[t] = (s > 0.0f) ? (1.0f / s) : 0.0f;
}

// ---------------------------------------------------------------------------
// 3-kernel exclusive scan over g_cnt (50176 padded elements).
// ---------------------------------------------------------------------------
__global__ void __launch_bounds__(256) scanA()
{
    __shared__ int sh[256];
    int t = threadIdx.x;
    int i = blockIdx.x * 256 + t;
    int c = (i < N_NODES) ? g_cnt[i] : 0;
    sh[t] = c;
#pragma unroll
    for (int off = 1; off < 256; off <<= 1) {
        __syncthreads();
        int v = (t >= off) ? sh[t - off] : 0;
        __syncthreads();
        sh[t] += v;
    }
    __syncthreads();
    g_excl[i] = sh[t] - c;
    if (t == 255) g_bsum[blockIdx.x] = sh[255];
}

__global__ void __launch_bounds__(256) scanB()
{
    __shared__ int sh[256];
    int t = threadIdx.x;
    int c = (t < SCAN_NB) ? g_bsum[t] : 0;
    sh[t] = c;
#pragma unroll
    for (int off = 1; off < 256; off <<= 1) {
        __syncthreads();
        int v = (t >= off) ? sh[t - off] : 0;
        __syncthreads();
        sh[t] += v;
    }
    __syncthreads();
    g_bbase[t] = sh[t] - c;
}

__global__ void __launch_bounds__(256) scanC()
{
    int i = blockIdx.x * blockDim.x + threadIdx.x;
    if (i > N_NODES) return;
    int v = g_excl[i] + g_bbase[i >> 8];
    g_csr[i] = v;
    if (i < N_NODES) g_cur[i] = v;
}

// ---------------------------------------------------------------------------
// Normalize attn in place (g_e[e,h] *= s_inv[row,h]) and scatter edge ids
// into CSR buckets (h==0 thread).
// ---------------------------------------------------------------------------
__global__ void __launch_bounds__(256) normalize_scatter(
    const int* __restrict__ row_idx, const int* __restrict__ col_idx)
{
    int t = blockIdx.x * blockDim.x + threadIdx.x;
    if (t >= N_EDGES * NHEADS) return;
    int e = t >> 3;
    int h = t & 7;

    int rw = __ldg(row_idx + e);
    g_e[t] *= __ldg(&g_s[rw * NHEADS + h]);

    if (h == 0) {
        int col = __ldg(col_idx + e);
        int pos = atomicAdd(&g_cur[col], 1);
        g_elist[pos] = e;
    }
}

// ---------------------------------------------------------------------------
// Gather: 16 threads per destination node, each owns one float4 output chunk.
// No atomics — register accumulation over the node's edge list, single write.
// ---------------------------------------------------------------------------
__global__ void __launch_bounds__(256) gather(
    const float* __restrict__ v0, const float* __restrict__ v1,
    float* __restrict__ out0, float* __restrict__ out1)
{
    int tid = threadIdx.x;
    int j = tid & 15;
    int n = blockIdx.x * 16 + (tid >> 4);   // grid sized exactly: 3125*16 = 50000

    int start = __ldg(&g_csr[n]);
    int end   = __ldg(&g_csr[n + 1]);

    float4 acc = make_float4(0.f, 0.f, 0.f, 0.f);

    if (j < 4) {
        int h0 = 2 * j, h1 = 2 * j + 1;
        for (int i = start; i < end; i++) {
            int e = __ldg(&g_elist[i]);
            const float* eb = g_e + (size_t)e * NHEADS;
            float a0 = __ldg(eb + h0);
            float a1 = __ldg(eb + h1);
            float4 v = __ldg((const float4*)(v0 + (size_t)e * 16 + 4 * j));
            acc.x += v.x * a0;
            acc.y += v.y * a0;
            acc.z += v.z * a1;
            acc.w += v.w * a1;
        }
        *(float4*)(out0 + (size_t)n * 16 + 4 * j) = acc;
    } else {
        int f0 = 4 * (j - 4);
        int hlo = f0 / 6;
        int hhi = (f0 + 3) / 6;
        bool s0 = ((f0 + 0) / 6 == hlo);
        bool s1 = ((f0 + 1) / 6 == hlo);
        bool s2 = ((f0 + 2) / 6 == hlo);
        bool s3 = ((f0 + 3) / 6 == hlo);
        for (int i = start; i < end; i++) {
            int e = __ldg(&g_elist[i]);
            const float* eb = g_e + (size_t)e * NHEADS;
            float alo = __ldg(eb + hlo);
            float ahi = (hhi == hlo) ? alo : __ldg(eb + hhi);
            float4 v = __ldg((const float4*)(v1 + (size_t)e * 48 + f0));
            acc.x += v.x * (s0 ? alo : ahi);
            acc.y += v.y * (s1 ? alo : ahi);
            acc.z += v.z * (s2 ? alo : ahi);
            acc.w += v.w * (s3 ? alo : ahi);
        }
        *(float4*)(out1 + (size_t)n * 48 + f0) = acc;
    }
}

// ---------------------------------------------------------------------------
// Launch.  Inputs: v0, v1, k0, k1, q0, q1, edge_index
// Output: out0 (N*16) ++ out1 (N*48)
// ---------------------------------------------------------------------------
extern "C" void kernel_launch(void* const* d_in, const int* in_sizes, int n_in,
                              void* d_out, int out_size)
{
    const float* v0 = (const float*)d_in[0];
    const float* v1 = (const float*)d_in[1];
    const float* k0 = (const float*)d_in[2];
    const float* k1 = (const float*)d_in[3];
    const float* q0 = (const float*)d_in[4];
    const float* q1 = (const float*)d_in[5];
    const int*   ei = (const int*)  d_in[6];
    const int* row_idx = ei;
    const int* col_idx = ei + N_EDGES;

    float* out0 = (float*)d_out;
    float* out1 = out0 + (size_t)N_NODES * MULT;

    void* s_addr = nullptr;
    void* c_addr = nullptr;
    cudaGetSymbolAddress(&s_addr, g_s);
    cudaGetSymbolAddress(&c_addr, g_cnt);

    cudaMemsetAsync(s_addr, 0, (size_t)N_NODES * NHEADS * sizeof(float));
    cudaMemsetAsync(c_addr, 0, (size_t)SCAN_TOT * sizeof(int));

    int n1 = N_EDGES * NHEADS;
    pass1_scores<<<(n1 + 255) / 256, 256>>>(k0, k1, q0, q1, row_idx, col_idx);

    int ns = N_NODES * NHEADS;
    invert_s<<<(ns + 255) / 256, 256>>>();

    scanA<<<SCAN_NB, 256>>>();
    scanB<<<1, 256>>>();
    scanC<<<(N_NODES + 256) / 256, 256>>>();

    normalize_scatter<<<(n1 + 255) / 256, 256>>>(row_idx, col_idx);

    gather<<<N_NODES / 16, 256>>>(v0, v1, out0, out1);
}

// round 3
// speedup vs baseline: 1.5987x; 1.5987x over previous
#include <cuda_runtime.h>
#include <math.h>

#define N_NODES 50000
#define N_EDGES 800000
#define NHEADS  8
#define MULT    16

// Scratch (device globals — no allocation allowed)
__device__ float g_e[(size_t)N_EDGES * NHEADS];   // exp scores (25.6 MB)
__device__ float g_s[(size_t)N_NODES * NHEADS];   // denominators -> inverted (1.6 MB)

// ---------------------------------------------------------------------------
// Pass 1: one thread per (edge, head) — proven near-DRAM-roofline (45us, 70%).
// ---------------------------------------------------------------------------
__global__ void __launch_bounds__(256) pass1_scores(
    const float* __restrict__ k0, const float* __restrict__ k1,
    const float* __restrict__ q0, const float* __restrict__ q1,
    const int* __restrict__ row_idx, const int* __restrict__ col_idx)
{
    int t = blockIdx.x * blockDim.x + threadIdx.x;
    if (t >= N_EDGES * NHEADS) return;
    int e = t >> 3;
    int h = t & 7;

    int col = __ldg(col_idx + e);

    float2 ka = *(const float2*)(k0 + (size_t)e   * 16 + 2 * h);
    float2 qa = *(const float2*)(q0 + (size_t)col * 16 + 2 * h);
    float dot = ka.x * qa.x + ka.y * qa.y;

    const float2* k1p = (const float2*)(k1 + (size_t)e   * 48 + 6 * h);
    const float2* q1p = (const float2*)(q1 + (size_t)col * 48 + 6 * h);
#pragma unroll
    for (int j = 0; j < 3; j++) {
        float2 kb = k1p[j];
        float2 qb = q1p[j];
        dot += kb.x * qb.x + kb.y * qb.y;
    }

    float w = expf(dot * 0.125f);   // 1/sqrt(64)
    g_e[t] = w;

    int rw = __ldg(row_idx + e);
    atomicAdd(&g_s[rw * NHEADS + h], w);
}

// ---------------------------------------------------------------------------
// Invert denominators once.
// ---------------------------------------------------------------------------
__global__ void __launch_bounds__(256) invert_s()
{
    int t = blockIdx.x * blockDim.x + threadIdx.x;
    if (t >= N_NODES * NHEADS) return;
    float s = g_s[t];
    g_s[t] = (s > 0.0f) ? (1.0f / s) : 0.0f;
}

// ---------------------------------------------------------------------------
// Pass 2: FOUR threads per edge. Thread q (0..3) owns heads {2q, 2q+1}:
//   - out0 float4 #q        (floats 4q..4q+3, heads 2q,2q+1)
//   - out1 float4 #3q..3q+2 (floats 12q..12q+11, heads (12q+f)/6 = 2q,2q+1)
// Loads: 1x LDG.64 attn pair, 1x LDG.64 s-inv pair, 1x LDG.128 v0 (warp-
// coalesced: lanes 0-3 cover one edge's contiguous 64B), 3x LDG.128 v1
// (warp covers 8 edges x 192B contiguous region). 4 vector REDs per thread.
// ---------------------------------------------------------------------------
__global__ void __launch_bounds__(256) pass2_scatter(
    const float* __restrict__ v0, const float* __restrict__ v1,
    const int* __restrict__ row_idx, const int* __restrict__ col_idx,
    float* __restrict__ out0, float* __restrict__ out1)
{
    int t = blockIdx.x * blockDim.x + threadIdx.x;
    if (t >= N_EDGES * 4) return;
    int e = t >> 2;
    int q = t & 3;

    int rw  = __ldg(row_idx + e);
    int col = __ldg(col_idx + e);

    // attn pair for heads 2q, 2q+1
    float2 ew = *(const float2*)(g_e + (size_t)e  * NHEADS + 2 * q);
    float2 sw = *(const float2*)(g_s + (size_t)rw * NHEADS + 2 * q);
    float a0 = ew.x * sw.x;   // head 2q
    float a1 = ew.y * sw.y;   // head 2q+1

    // ---- out0 chunk q: v0 floats 4q..4q+3, heads {2q,2q,2q+1,2q+1} ----
    {
        float4 v = __ldg((const float4*)(v0 + (size_t)e * 16 + 4 * q));
        float* p = out0 + (size_t)col * 16 + 4 * q;
        asm volatile("red.global.add.v4.f32 [%0], {%1, %2, %3, %4};"
                     :: "l"(p), "f"(v.x * a0), "f"(v.y * a0),
                        "f"(v.z * a1), "f"(v.w * a1) : "memory");
    }

    // ---- out1 chunks 3q..3q+2: v1 floats 12q..12q+11 ----
    // f = 12q + u (u=0..11): head = (12q+u)/6 = 2q + u/6  -> a0 for u<6, a1 for u>=6
    const float* vb = v1 + (size_t)e * 48 + 12 * q;
    float* pb = out1 + (size_t)col * 48 + 12 * q;

    {
        float4 v = __ldg((const float4*)(vb));        // u = 0..3  -> all a0
        asm volatile("red.global.add.v4.f32 [%0], {%1, %2, %3, %4};"
                     :: "l"(pb), "f"(v.x * a0), "f"(v.y * a0),
                        "f"(v.z * a0), "f"(v.w * a0) : "memory");
    }
    {
        float4 v = __ldg((const float4*)(vb + 4));    // u = 4..7  -> a0,a0,a1,a1
        asm volatile("red.global.add.v4.f32 [%0], {%1, %2, %3, %4};"
                     :: "l"(pb + 4), "f"(v.x * a0), "f"(v.y * a0),
                        "f"(v.z * a1), "f"(v.w * a1) : "memory");
    }
    {
        float4 v = __ldg((const float4*)(vb + 8));    // u = 8..11 -> all a1
        asm volatile("red.global.add.v4.f32 [%0], {%1, %2, %3, %4};"
                     :: "l"(pb + 8), "f"(v.x * a1), "f"(v.y * a1),
                        "f"(v.z * a1), "f"(v.w * a1) : "memory");
    }
}

// ---------------------------------------------------------------------------
// Launch.  Inputs: v0, v1, k0, k1, q0, q1, edge_index
// Output: out0 (N*16) ++ out1 (N*48)
// ---------------------------------------------------------------------------
extern "C" void kernel_launch(void* const* d_in, const int* in_sizes, int n_in,
                              void* d_out, int out_size)
{
    const float* v0 = (const float*)d_in[0];
    const float* v1 = (const float*)d_in[1];
    const float* k0 = (const float*)d_in[2];
    const float* k1 = (const float*)d_in[3];
    const float* q0 = (const float*)d_in[4];
    const float* q1 = (const float*)d_in[5];
    const int*   ei = (const int*)  d_in[6];
    const int* row_idx = ei;             // edge_index[0]
    const int* col_idx = ei + N_EDGES;   // edge_index[1]

    float* out0 = (float*)d_out;
    float* out1 = out0 + (size_t)N_NODES * MULT;

    void* s_addr = nullptr;
    cudaGetSymbolAddress(&s_addr, g_s);

    cudaMemsetAsync(s_addr, 0, (size_t)N_NODES * NHEADS * sizeof(float));
    cudaMemsetAsync(d_out, 0, (size_t)out_size * sizeof(float));

    int n1 = N_EDGES * NHEADS;
    pass1_scores<<<(n1 + 255) / 256, 256>>>(k0, k1, q0, q1, row_idx, col_idx);

    int ns = N_NODES * NHEADS;
    invert_s<<<(ns + 255) / 256, 256>>>();

    int n2 = N_EDGES * 4;
    pass2_scatter<<<(n2 + 255) / 256, 256>>>(v0, v1, row_idx, col_idx, out0, out1);
}